// round 16
// baseline (speedup 1.0000x reference)
#include <cuda_runtime.h>
#include <math.h>

#define SS 7
#define NPTS 49
#define CCH 256
#define CSPLIT 2          // CTAs per ROI
#define CPER (CCH / CSPLIT)

__global__ __launch_bounds__(256) void oriented_roi_align_kernel(
    const float* __restrict__ f0, const float* __restrict__ f1,
    const float* __restrict__ f2, const float* __restrict__ f3,
    const float* __restrict__ rois, const int* __restrict__ levels,
    float* __restrict__ out, int N, int total)
{
    // Interleaved mapping: consecutive CTAs -> consecutive ROIs (uniform level mix per wave)
    const int bid  = blockIdx.x;
    const int roi  = bid % total;
    const int half = bid / total;
    const int bb   = roi / N;
    const int tid  = threadIdx.x;

    __shared__ float s_w00[NPTS], s_w01[NPTS], s_w10[NPTS], s_w11[NPTS];
    __shared__ int   s_o00[NPTS], s_o01[NPTS], s_o10[NPTS], s_o11[NPTS];

    const int lvl = __ldg(levels + roi);
    int H; float scale; const float* fbase;
    switch (lvl) {
        case 0:  H = 256; scale = 0.25f;     fbase = f0; break;
        case 1:  H = 128; scale = 0.125f;    fbase = f1; break;
        case 2:  H = 64;  scale = 0.0625f;   fbase = f2; break;
        default: H = 32;  scale = 0.03125f;  fbase = f3; break;
    }
    const int HW = H * H;
    const float* base = fbase + (size_t)bb * CCH * HW;
    float* op = out + (size_t)roi * CCH * NPTS;

    if (tid < NPTS) {
        const float* r = rois + (size_t)roi * 6;
        const float x = r[0], y = r[1], w = r[2], h = r[3], a = r[4], b = r[5];

        // ---- parallelogram -> rectangle (matches reference) ----
        const float d1 = sqrtf(4.f * a * a + h * h);   // |v3 - v1|
        const float d2 = sqrtf(w * w + 4.f * b * b);   // |v4 - v2|
        const float eps = 1e-6f;
        float V0x, V0y, V1x, V1y, V2x, V2y;
        if (d1 > d2) {
            const float sA = d1 / (d2 + eps);
            V0x = x + a;          V0y = y + 0.5f * h;
            V1x = (x + 0.5f * w) + (sA - 1.f) * (0.5f * w);
            V1y = (y + b)        + (sA - 1.f) * b;
            V2x = x - a;          V2y = y - 0.5f * h;
        } else {
            const float sB = d2 / (d1 + eps);
            V0x = (x + a)        + (sB - 1.f) * a;
            V0y = (y + 0.5f * h) + (sB - 1.f) * (0.5f * h);
            V1x = x + 0.5f * w;   V1y = y + b;
            V2x = (x - a)        - (sB - 1.f) * a;
            V2y = (y - 0.5f * h) - (sB - 1.f) * (0.5f * h);
        }
        const float hre = sqrtf((V1x - V0x) * (V1x - V0x) + (V1y - V0y) * (V1y - V0y));
        const float wre = sqrtf((V2x - V1x) * (V2x - V1x) + (V2y - V1y) * (V2y - V1y));
        float theta = atan2f(V1y - V2y, V1x - V2x);
        const float PI2 = 1.5707963267948966f;
        theta = fminf(fmaxf(theta, -PI2), PI2);
        const float ct = cosf(theta), st = sinf(theta);

        // ---- sample point for this (i, j) ----
        const int   i  = tid / SS, j = tid % SS;
        const float tj = (float)j / 6.f - 0.5f;
        const float ti = (float)i / 6.f - 0.5f;
        const float gx = wre * scale * tj;
        const float gy = hre * scale * ti;
        const float rx =  gx * ct + gy * st + x * scale;
        const float ry = -gx * st + gy * ct + y * scale;

        const float Wf  = (float)H;
        const float inv = 1.f / (float)(H - 1);
        const float gxn = rx * scale * inv * 2.f - 1.f;
        const float gyn = ry * scale * inv * 2.f - 1.f;
        const float px = ((gxn + 1.f) * Wf - 1.f) * 0.5f;
        const float py = ((gyn + 1.f) * Wf - 1.f) * 0.5f;

        const float x0f = floorf(px), y0f = floorf(py);
        const float wx = px - x0f, wy = py - y0f;
        const int x0 = min(max((int)x0f, 0), H - 1);
        const int x1 = min(x0 + 1, H - 1);
        const int y0 = min(max((int)y0f, 0), H - 1);
        const int y1 = min(y0 + 1, H - 1);

        s_o00[tid] = y0 * H + x0;
        s_o01[tid] = y0 * H + x1;
        s_o10[tid] = y1 * H + x0;
        s_o11[tid] = y1 * H + x1;
        s_w00[tid] = (1.f - wx) * (1.f - wy);
        s_w01[tid] = wx * (1.f - wy);
        s_w10[tid] = (1.f - wx) * wy;
        s_w11[tid] = wx * wy;
    }
    __syncthreads();

    const int warp = tid >> 5;
    const int lane = tid & 31;

    // Register-cache the (up to) two points this lane owns.
    const int  pA = lane;
    const bool hasB = (32 + lane) < NPTS;
    const int  pB = hasB ? 32 + lane : 0;   // clamped: B loads always safe

    const int   a00 = s_o00[pA], a01 = s_o01[pA], a10 = s_o10[pA], a11 = s_o11[pA];
    const float wa00 = s_w00[pA], wa01 = s_w01[pA], wa10 = s_w10[pA], wa11 = s_w11[pA];
    const int   b00 = s_o00[pB], b01 = s_o01[pB], b10 = s_o10[pB], b11 = s_o11[pB];
    const float wb00 = s_w00[pB], wb01 = s_w01[pB], wb10 = s_w10[pB], wb11 = s_w11[pB];

    // Channel loop over this CTA's half: c = cbase + warp + 8k, unrolled x2.
    // All 16 loads issue unconditionally (branch-free) so ptxas front-batches them;
    // only the B stores are predicated.
    const int cbase = half * CPER;
    const int cend  = cbase + CPER;
    #pragma unroll 1
    for (int c = cbase + warp; c < cend; c += 16) {
        const float* pl0 = base + (size_t)c * HW;
        const float* pl1 = pl0 + (size_t)8 * HW;
        float* o0 = op + c * NPTS;
        float* o1 = o0 + 8 * NPTS;

        // ---- 16 independent loads, no branch between batches ----
        const float v0a00 = __ldg(pl0 + a00), v0a01 = __ldg(pl0 + a01);
        const float v0a10 = __ldg(pl0 + a10), v0a11 = __ldg(pl0 + a11);
        const float v1a00 = __ldg(pl1 + a00), v1a01 = __ldg(pl1 + a01);
        const float v1a10 = __ldg(pl1 + a10), v1a11 = __ldg(pl1 + a11);
        const float v0b00 = __ldg(pl0 + b00), v0b01 = __ldg(pl0 + b01);
        const float v0b10 = __ldg(pl0 + b10), v0b11 = __ldg(pl0 + b11);
        const float v1b00 = __ldg(pl1 + b00), v1b01 = __ldg(pl1 + b01);
        const float v1b10 = __ldg(pl1 + b10), v1b11 = __ldg(pl1 + b11);

        o0[pA] = v0a00 * wa00 + v0a01 * wa01 + v0a10 * wa10 + v0a11 * wa11;
        o1[pA] = v1a00 * wa00 + v1a01 * wa01 + v1a10 * wa10 + v1a11 * wa11;
        if (hasB) {
            o0[pB] = v0b00 * wb00 + v0b01 * wb01 + v0b10 * wb10 + v0b11 * wb11;
            o1[pB] = v1b00 * wb00 + v1b01 * wb01 + v1b10 * wb10 + v1b11 * wb11;
        }
    }
}

extern "C" void kernel_launch(void* const* d_in, const int* in_sizes, int n_in,
                              void* d_out, int out_size) {
    const float* f0 = (const float*)d_in[0];
    const float* f1 = (const float*)d_in[1];
    const float* f2 = (const float*)d_in[2];
    const float* f3 = (const float*)d_in[3];
    const float* rois = (const float*)d_in[4];
    const int* levels = (const int*)d_in[5];
    float* out = (float*)d_out;

    const int B = in_sizes[0] / (256 * 256 * 256);
    const int total = in_sizes[5];        // B*N rois
    const int N = total / (B > 0 ? B : 1);

    oriented_roi_align_kernel<<<total * CSPLIT, 256>>>(f0, f1, f2, f3, rois, levels, out, N, total);
}

// round 17
// speedup vs baseline: 1.0551x; 1.0551x over previous
#include <cuda_runtime.h>
#include <math.h>

#define SS 7
#define NPTS 49
#define CCH 256
#define CSPLIT 2          // CTAs per ROI
#define CPER (CCH / CSPLIT)

__global__ __launch_bounds__(256) void oriented_roi_align_kernel(
    const float* __restrict__ f0, const float* __restrict__ f1,
    const float* __restrict__ f2, const float* __restrict__ f3,
    const float* __restrict__ rois, const int* __restrict__ levels,
    float* __restrict__ out, int N)
{
    const int roi  = blockIdx.x >> 1;     // roi = b*N + n
    const int half = blockIdx.x & 1;      // which channel half
    const int bb   = roi / N;
    const int tid  = threadIdx.x;

    __shared__ float s_w00[NPTS], s_w01[NPTS], s_w10[NPTS], s_w11[NPTS];
    __shared__ int   s_o00[NPTS], s_o01[NPTS], s_o10[NPTS], s_o11[NPTS];

    const int lvl = __ldg(levels + roi);
    int H; float scale; const float* fbase;
    switch (lvl) {
        case 0:  H = 256; scale = 0.25f;     fbase = f0; break;
        case 1:  H = 128; scale = 0.125f;    fbase = f1; break;
        case 2:  H = 64;  scale = 0.0625f;   fbase = f2; break;
        default: H = 32;  scale = 0.03125f;  fbase = f3; break;
    }
    const int HW = H * H;
    const float* base = fbase + (size_t)bb * CCH * HW;
    float* op = out + (size_t)roi * CCH * NPTS;

    if (tid < NPTS) {
        const float* r = rois + (size_t)roi * 6;
        const float x = r[0], y = r[1], w = r[2], h = r[3], a = r[4], b = r[5];

        // ---- parallelogram -> rectangle (matches reference) ----
        const float d1 = sqrtf(4.f * a * a + h * h);   // |v3 - v1|
        const float d2 = sqrtf(w * w + 4.f * b * b);   // |v4 - v2|
        const float eps = 1e-6f;
        float V0x, V0y, V1x, V1y, V2x, V2y;
        if (d1 > d2) {
            const float sA = d1 / (d2 + eps);
            V0x = x + a;          V0y = y + 0.5f * h;
            V1x = (x + 0.5f * w) + (sA - 1.f) * (0.5f * w);
            V1y = (y + b)        + (sA - 1.f) * b;
            V2x = x - a;          V2y = y - 0.5f * h;
        } else {
            const float sB = d2 / (d1 + eps);
            V0x = (x + a)        + (sB - 1.f) * a;
            V0y = (y + 0.5f * h) + (sB - 1.f) * (0.5f * h);
            V1x = x + 0.5f * w;   V1y = y + b;
            V2x = (x - a)        - (sB - 1.f) * a;
            V2y = (y - 0.5f * h) - (sB - 1.f) * (0.5f * h);
        }
        const float hre = sqrtf((V1x - V0x) * (V1x - V0x) + (V1y - V0y) * (V1y - V0y));
        const float wre = sqrtf((V2x - V1x) * (V2x - V1x) + (V2y - V1y) * (V2y - V1y));
        float theta = atan2f(V1y - V2y, V1x - V2x);
        const float PI2 = 1.5707963267948966f;
        theta = fminf(fmaxf(theta, -PI2), PI2);
        const float ct = cosf(theta), st = sinf(theta);

        // ---- sample point for this (i, j) ----
        const int   i  = tid / SS, j = tid % SS;
        const float tj = (float)j / 6.f - 0.5f;
        const float ti = (float)i / 6.f - 0.5f;
        const float gx = wre * scale * tj;
        const float gy = hre * scale * ti;
        const float rx =  gx * ct + gy * st + x * scale;
        const float ry = -gx * st + gy * ct + y * scale;

        const float Wf  = (float)H;
        const float inv = 1.f / (float)(H - 1);
        const float gxn = rx * scale * inv * 2.f - 1.f;
        const float gyn = ry * scale * inv * 2.f - 1.f;
        const float px = ((gxn + 1.f) * Wf - 1.f) * 0.5f;
        const float py = ((gyn + 1.f) * Wf - 1.f) * 0.5f;

        const float x0f = floorf(px), y0f = floorf(py);
        const float wx = px - x0f, wy = py - y0f;
        const int x0 = min(max((int)x0f, 0), H - 1);
        const int x1 = min(x0 + 1, H - 1);
        const int y0 = min(max((int)y0f, 0), H - 1);
        const int y1 = min(y0 + 1, H - 1);

        s_o00[tid] = y0 * H + x0;
        s_o01[tid] = y0 * H + x1;
        s_o10[tid] = y1 * H + x0;
        s_o11[tid] = y1 * H + x1;
        s_w00[tid] = (1.f - wx) * (1.f - wy);
        s_w01[tid] = wx * (1.f - wy);
        s_w10[tid] = (1.f - wx) * wy;
        s_w11[tid] = wx * wy;
    }
    __syncthreads();

    const int warp = tid >> 5;
    const int lane = tid & 31;

    // Register-cache the (up to) two points this lane owns.
    const int  pA = lane;
    const bool hasB = (32 + lane) < NPTS;
    const int  pB = hasB ? 32 + lane : 0;   // clamped: B loads always safe

    const int   a00 = s_o00[pA], a01 = s_o01[pA], a10 = s_o10[pA], a11 = s_o11[pA];
    const float wa00 = s_w00[pA], wa01 = s_w01[pA], wa10 = s_w10[pA], wa11 = s_w11[pA];
    const int   b00 = s_o00[pB], b01 = s_o01[pB], b10 = s_o10[pB], b11 = s_o11[pB];
    const float wb00 = s_w00[pB], wb01 = s_w01[pB], wb10 = s_w10[pB], wb11 = s_w11[pB];

    // Channel loop over this CTA's half: c = cbase + warp + 8k, unrolled x2.
    // All 16 loads issue unconditionally (branch-free) so ptxas front-batches them;
    // only the B stores are predicated.
    const int cbase = half * CPER;
    const int cend  = cbase + CPER;
    #pragma unroll 1
    for (int c = cbase + warp; c < cend; c += 16) {
        const float* pl0 = base + (size_t)c * HW;
        const float* pl1 = pl0 + (size_t)8 * HW;
        float* o0 = op + c * NPTS;
        float* o1 = o0 + 8 * NPTS;

        // ---- 16 independent loads, no branch between batches ----
        const float v0a00 = __ldg(pl0 + a00), v0a01 = __ldg(pl0 + a01);
        const float v0a10 = __ldg(pl0 + a10), v0a11 = __ldg(pl0 + a11);
        const float v1a00 = __ldg(pl1 + a00), v1a01 = __ldg(pl1 + a01);
        const float v1a10 = __ldg(pl1 + a10), v1a11 = __ldg(pl1 + a11);
        const float v0b00 = __ldg(pl0 + b00), v0b01 = __ldg(pl0 + b01);
        const float v0b10 = __ldg(pl0 + b10), v0b11 = __ldg(pl0 + b11);
        const float v1b00 = __ldg(pl1 + b00), v1b01 = __ldg(pl1 + b01);
        const float v1b10 = __ldg(pl1 + b10), v1b11 = __ldg(pl1 + b11);

        o0[pA] = v0a00 * wa00 + v0a01 * wa01 + v0a10 * wa10 + v0a11 * wa11;
        o1[pA] = v1a00 * wa00 + v1a01 * wa01 + v1a10 * wa10 + v1a11 * wa11;
        if (hasB) {
            o0[pB] = v0b00 * wb00 + v0b01 * wb01 + v0b10 * wb10 + v0b11 * wb11;
            o1[pB] = v1b00 * wb00 + v1b01 * wb01 + v1b10 * wb10 + v1b11 * wb11;
        }
    }
}

extern "C" void kernel_launch(void* const* d_in, const int* in_sizes, int n_in,
                              void* d_out, int out_size) {
    const float* f0 = (const float*)d_in[0];
    const float* f1 = (const float*)d_in[1];
    const float* f2 = (const float*)d_in[2];
    const float* f3 = (const float*)d_in[3];
    const float* rois = (const float*)d_in[4];
    const int* levels = (const int*)d_in[5];
    float* out = (float*)d_out;

    const int B = in_sizes[0] / (256 * 256 * 256);
    const int total = in_sizes[5];        // B*N rois
    const int N = total / (B > 0 ? B : 1);

    oriented_roi_align_kernel<<<total * CSPLIT, 256>>>(f0, f1, f2, f3, rois, levels, out, N);
}